// round 11
// baseline (speedup 1.0000x reference)
#include <cuda_runtime.h>
#include <cuda_fp16.h>
#include <float.h>
#include <stdint.h>

#define NROWS   262144
#define DIM     64
#define NCODES  512
#define NELEM   (NROWS * DIM)
#define TM      128
#define NTILES  (NROWS / TM)     // 2048
#define GRID    152
#define NTHREADS 320             // 8 compute warps + 2 loader warps
#define MAXC    8

#define RSTRIDE_A 72             // halves per padded A row (144 B)

// SMEM byte offsets
#define SM_DT    0               // dictT fp32 [512][64]            (131072)
#define SM_A     131072          // A hi 2 x [128][72] f16 (also B staging) (36864)
#define SM_NS    167936          // code norms f32[512]             (2048)
#define SM_RN    169984          // row norms 2 x f32[128]          (1024)
#define SM_THR   171008          // row thresholds 2 x f32[128]     (1024)
#define SM_CODE  172032          // codes 2 x int[128]              (1024)
#define SM_RD1   173056          // per-rt best 2 x [16][8] f32     (1024)
#define SM_RDK   174080          // per-rt bestk 2 x [16][8] int    (1024)
#define SM_GBD   175104          // global best d f32[128]          (512)
#define SM_GBK   175616          // global best k int[128]          (512)
#define SM_CNT   176128          // cand count int[128]             (512)
#define SM_CK    176640          // cand codes int[128][8]          (4096)
#define SM_SIZE  180736

#define ABUF_SZ  18432           // one A buffer (128*72*2)

__device__ float g_partials[GRID];

__device__ __forceinline__ uint32_t smem_u32(const void* p) {
    uint32_t a;
    asm("{ .reg .u64 t; cvta.to.shared.u64 t, %1; cvt.u32.u64 %0, t; }" : "=r"(a) : "l"(p));
    return a;
}

#define LDSM4(r, addr) \
    asm volatile("ldmatrix.sync.aligned.m8n8.x4.shared.b16 {%0,%1,%2,%3}, [%4];" \
        : "=r"((r)[0]), "=r"((r)[1]), "=r"((r)[2]), "=r"((r)[3]) : "r"(addr))

#define MMA16816(c, a, b0, b1) \
    asm volatile("mma.sync.aligned.m16n8k16.row.col.f32.f16.f16.f32 " \
        "{%0,%1,%2,%3}, {%4,%5,%6,%7}, {%8,%9}, {%0,%1,%2,%3};" \
        : "+f"((c)[0]), "+f"((c)[1]), "+f"((c)[2]), "+f"((c)[3]) \
        : "r"((a)[0]), "r"((a)[1]), "r"((a)[2]), "r"((a)[3]), "r"(b0), "r"(b1))

// named barriers: 3 = block-wide (320), 1 = compute-only (256)
#define BAR_ALL()  asm volatile("bar.sync 3, 320;" ::: "memory")
#define BAR_CMP()  asm volatile("bar.sync 1, 256;" ::: "memory")

extern __shared__ char smem_raw[];

__global__ __launch_bounds__(NTHREADS, 1) void vq_kernel(
    const float* __restrict__ x, const float* __restrict__ dict,
    float* __restrict__ out)
{
    char* sm = smem_raw;
    const uint32_t smu = smem_u32(sm);

    float* dictT   = (float*)(sm + SM_DT);
    float* ns_s    = (float*)(sm + SM_NS);
    float* rn_s    = (float*)(sm + SM_RN);    // [2][128]
    float* thr_s   = (float*)(sm + SM_THR);   // [2][128]
    int*   codes_s = (int*)(sm + SM_CODE);    // [2][128]
    float* rd1_s   = (float*)(sm + SM_RD1);   // [2][16][8]
    int*   rdk_s   = (int*)(sm + SM_RDK);
    float* gbd_s   = (float*)(sm + SM_GBD);   // [128]
    int*   gbk_s   = (int*)(sm + SM_GBK);
    int*   cnt_s   = (int*)(sm + SM_CNT);     // [128]
    int*   ck_s    = (int*)(sm + SM_CK);      // [128][MAXC]

    const int tid  = threadIdx.x;
    const int w    = tid >> 5;
    const int lane = tid & 31;

    // ---- build dictT fp32 [k][d] + code norms (dict is [D=64][K=512]) ----
    {
        const float4* d4 = (const float4*)dict;
        for (int i = tid; i < 64 * 128; i += NTHREADS) {
            int d = i >> 7, kq = i & 127;
            float4 v = d4[d * 128 + kq];
            dictT[(kq * 4 + 0) * 64 + d] = v.x;
            dictT[(kq * 4 + 1) * 64 + d] = v.y;
            dictT[(kq * 4 + 2) * 64 + d] = v.z;
            dictT[(kq * 4 + 3) * 64 + d] = v.w;
        }
        for (int k = tid; k < NCODES; k += NTHREADS) {
            float s = 0.0f;
            #pragma unroll 8
            for (int d = 0; d < DIM; d++) {
                float v = dict[d * NCODES + k];
                s = fmaf(v, v, s);
            }
            ns_s[k] = s;
        }
    }
    __syncthreads();

    // lane-constant fragment addressing
    const int arow = (lane & 7) + (lane & 8);
    const int acol = (lane & 16) ? 8 : 0;
    const int bn   = (lane & 7) + ((lane & 16) >> 1);
    const int bk   = (lane & 8);
    const int crow = lane >> 2;
    const int ccol = 2 * (lane & 3);

    // ---- stage B hi (fp16) in two halves through the A region; LDSM to regs ----
    uint32_t BHf[4][4][4];   // [p][kc][frag]
    __half* stage = (__half*)(sm + SM_A);
    #pragma unroll 1
    for (int half = 0; half < 2; half++) {
        for (int i = tid; i < 256 * 64; i += NTHREADS) {
            int k = i >> 6, d = i & 63;
            stage[k * 64 + d] = __float2half_rn(dictT[(half * 256 + k) * 64 + d]);
        }
        __syncthreads();
        if (w >= half * 4 && w < half * 4 + 4) {
            const uint32_t base = smu + SM_A +
                (uint32_t)(((w - half * 4) * 64 + bn) * 64 + bk) * 2;
            #pragma unroll
            for (int p = 0; p < 4; p++)
                #pragma unroll
                for (int kc = 0; kc < 4; kc++)
                    LDSM4(BHf[p][kc], base + (uint32_t)(p * 16) * 128 + kc * 32);
        }
        __syncthreads();
    }

    if (tid < 256) {
        // ================= COMPUTE WARPS =================
        const uint32_t aOff0 = (uint32_t)(arow * RSTRIDE_A + acol) * 2;
        float loss_acc = 0.0f;

        #pragma unroll 1
        for (int j = 0, tile = blockIdx.x; tile < NTILES; tile += GRID, j++) {
            BAR_ALL();                         // A[j&1], rn, thr ready; codes consumed
            const int b = j & 1;
            const uint32_t aBase = smu + SM_A + (uint32_t)(b * ABUF_SZ) + aOff0;
            if (tid < TM) cnt_s[tid] = 0;

            #pragma unroll 1
            for (int rt = 0; rt < 8; rt++) {
                const int par = rt & 1;
                const uint32_t ab = aBase + (uint32_t)(rt * 16) * (RSTRIDE_A * 2);

                float f[8][4];
                #pragma unroll
                for (int nt = 0; nt < 8; nt++)
                    #pragma unroll
                    for (int q = 0; q < 4; q++) f[nt][q] = 0.0f;

                #pragma unroll
                for (int kc = 0; kc < 4; kc++) {
                    uint32_t aH[4];
                    LDSM4(aH, ab + kc * 32);
                    #pragma unroll
                    for (int nt = 0; nt < 8; nt++)
                        MMA16816(f[nt], aH, BHf[nt >> 1][kc][(nt & 1) * 2], BHf[nt >> 1][kc][(nt & 1) * 2 + 1]);
                }

                const int rowa = rt * 16 + crow;
                const float rn0 = rn_s[b * 128 + rowa];
                const float rn1 = rn_s[b * 128 + rowa + 8];
                float best0 = FLT_MAX, best1 = FLT_MAX;
                int   bk0 = 0, bk1 = 0;

                #pragma unroll
                for (int nt = 0; nt < 8; nt++) {
                    int n = w * 64 + nt * 8 + ccol;
                    float nk0 = ns_s[n], nk1 = ns_s[n + 1];
                    f[nt][0] = fmaf(-2.0f, f[nt][0], rn0 + nk0);
                    f[nt][1] = fmaf(-2.0f, f[nt][1], rn0 + nk1);
                    f[nt][2] = fmaf(-2.0f, f[nt][2], rn1 + nk0);
                    f[nt][3] = fmaf(-2.0f, f[nt][3], rn1 + nk1);
                    if (f[nt][0] < best0) { best0 = f[nt][0]; bk0 = n; }
                    if (f[nt][1] < best0) { best0 = f[nt][1]; bk0 = n + 1; }
                    if (f[nt][2] < best1) { best1 = f[nt][2]; bk1 = n; }
                    if (f[nt][3] < best1) { best1 = f[nt][3]; bk1 = n + 1; }
                }
                #pragma unroll
                for (int off = 1; off <= 2; off <<= 1) {
                    float od0 = __shfl_xor_sync(0xffffffffu, best0, off);
                    int   ok0 = __shfl_xor_sync(0xffffffffu, bk0, off);
                    if (od0 < best0 || (od0 == best0 && ok0 < bk0)) { best0 = od0; bk0 = ok0; }
                    float od1 = __shfl_xor_sync(0xffffffffu, best1, off);
                    int   ok1 = __shfl_xor_sync(0xffffffffu, bk1, off);
                    if (od1 < best1 || (od1 == best1 && ok1 < bk1)) { best1 = od1; bk1 = ok1; }
                }
                if ((lane & 3) == 0) {
                    rd1_s[(par * 16 + crow) * 8 + w] = best0;
                    rdk_s[(par * 16 + crow) * 8 + w] = bk0;
                    rd1_s[(par * 16 + crow + 8) * 8 + w] = best1;
                    rdk_s[(par * 16 + crow + 8) * 8 + w] = bk1;
                }
                BAR_CMP();                     // rd[par] complete

                // global best merge (ascending w = ascending k; strict < keeps lowest k)
                float gd0 = rd1_s[(par * 16 + crow) * 8];
                int   gk0 = rdk_s[(par * 16 + crow) * 8];
                float gd1 = rd1_s[(par * 16 + crow + 8) * 8];
                int   gk1 = rdk_s[(par * 16 + crow + 8) * 8];
                #pragma unroll
                for (int q = 1; q < 8; q++) {
                    float c0 = rd1_s[(par * 16 + crow) * 8 + q];
                    if (c0 < gd0) { gd0 = c0; gk0 = rdk_s[(par * 16 + crow) * 8 + q]; }
                    float c1 = rd1_s[(par * 16 + crow + 8) * 8 + q];
                    if (c1 < gd1) { gd1 = c1; gk1 = rdk_s[(par * 16 + crow + 8) * 8 + q]; }
                }
                if (w == 0 && (lane & 3) == 0) {
                    gbd_s[rowa] = gd0;     gbk_s[rowa] = gk0;
                    gbd_s[rowa + 8] = gd1; gbk_s[rowa + 8] = gk1;
                }
                const float th0 = gd0 + thr_s[b * 128 + rowa];
                const float th1 = gd1 + thr_s[b * 128 + rowa + 8];
                #pragma unroll
                for (int nt = 0; nt < 8; nt++) {
                    int n = w * 64 + nt * 8 + ccol;
                    if (f[nt][0] <= th0) { int s = atomicAdd(&cnt_s[rowa], 1); if (s < MAXC) ck_s[rowa * MAXC + s] = n; }
                    if (f[nt][1] <= th0) { int s = atomicAdd(&cnt_s[rowa], 1); if (s < MAXC) ck_s[rowa * MAXC + s] = n + 1; }
                    if (f[nt][2] <= th1) { int s = atomicAdd(&cnt_s[rowa + 8], 1); if (s < MAXC) ck_s[(rowa + 8) * MAXC + s] = n; }
                    if (f[nt][3] <= th1) { int s = atomicAdd(&cnt_s[rowa + 8], 1); if (s < MAXC) ck_s[(rowa + 8) * MAXC + s] = n + 1; }
                }
            }
            BAR_CMP();                         // all candidates visible

            // ---- refine: warp w owns rows i*8+w ----
            const long row0 = (long)tile * TM;
            #pragma unroll 1
            for (int i = 0; i < 16; i++) {
                const int r = i * 8 + w;
                const int c = cnt_s[r];
                if (c <= 1) {
                    if (lane == 0) { codes_s[b * 128 + r] = gbk_s[r]; loss_acc += gbd_s[r]; }
                    continue;
                }
                const float* xp = x + (row0 + r) * DIM;
                float x0 = xp[lane], x1 = xp[lane + 32];
                float rnr = rn_s[b * 128 + r];
                float bd = FLT_MAX; int bkk = 0;
                if (c <= MAXC) {
                    #pragma unroll 1
                    for (int q = 0; q < c; q++) {
                        int k = ck_s[r * MAXC + q];
                        const float* W = dictT + k * 64;
                        float p = fmaf(x1, W[lane + 32], x0 * W[lane]);
                        #pragma unroll
                        for (int o = 16; o > 0; o >>= 1) p += __shfl_xor_sync(0xffffffffu, p, o);
                        float dv = fmaf(-2.0f, p, rnr + ns_s[k]);
                        if (dv < bd || (dv == bd && k < bkk)) { bd = dv; bkk = k; }
                    }
                } else {
                    #pragma unroll 1
                    for (int k = 0; k < NCODES; k++) {
                        const float* W = dictT + k * 64;
                        float p = fmaf(x1, W[lane + 32], x0 * W[lane]);
                        #pragma unroll
                        for (int o = 16; o > 0; o >>= 1) p += __shfl_xor_sync(0xffffffffu, p, o);
                        float dv = fmaf(-2.0f, p, rnr + ns_s[k]);
                        if (dv < bd) { bd = dv; bkk = k; }
                    }
                }
                if (lane == 0) { codes_s[b * 128 + r] = bkk; loss_acc += bd; }
            }
        }
        BAR_ALL();                             // publish last codes to loaders

        // ---- per-CTA loss reduction ----
        float v = loss_acc;
        #pragma unroll
        for (int o = 16; o > 0; o >>= 1) v += __shfl_down_sync(0xffffffffu, v, o);
        if (lane == 0) gbd_s[w] = v;
        BAR_CMP();
        if (tid == 0) {
            float t = 0.0f;
            #pragma unroll
            for (int i = 0; i < 8; i++) t += gbd_s[i];
            g_partials[blockIdx.x] = t;
        }
    } else {
        // ================= LOADER WARPS (tid 256..319) =================
        const int lt = tid - 256;               // 0..63, owns rows lt, lt+64
        __half* AhB = (__half*)(sm + SM_A);

        // prologue: fill buffer 0 with tile blockIdx.x
        {
            const long row0 = (long)blockIdx.x * TM;
            #pragma unroll
            for (int s = 0; s < 2; s++) {
                int r = lt + s * 64;
                const float4* xr = (const float4*)(x + (row0 + r) * DIM);
                float rn = 0.0f, sm_a = 0.0f, sh_a = 0.0f;
                #pragma unroll
                for (int jj = 0; jj < 16; jj++) {
                    float4 v = xr[jj];
                    rn = fmaf(v.x, v.x, rn); rn = fmaf(v.y, v.y, rn);
                    rn = fmaf(v.z, v.z, rn); rn = fmaf(v.w, v.w, rn);
                    __half2 h01 = __floats2half2_rn(v.x, v.y);
                    __half2 h23 = __floats2half2_rn(v.z, v.w);
                    float2 a01 = __half22float2(h01), a23 = __half22float2(h23);
                    sm_a += fabsf(v.x - a01.x) + fabsf(v.y - a01.y)
                          + fabsf(v.z - a23.x) + fabsf(v.w - a23.y);
                    sh_a += fabsf(a01.x) + fabsf(a01.y) + fabsf(a23.x) + fabsf(a23.y);
                    int off = r * RSTRIDE_A + jj * 4;
                    *(__half2*)(AhB + off)     = h01;
                    *(__half2*)(AhB + off + 2) = h23;
                }
                rn_s[r] = rn;
                thr_s[r] = 2.0f * (0.051f * sm_a + 1.6e-5f * sh_a) + 2e-4f;
            }
        }

        long prev_row0 = 0;
        #pragma unroll 1
        for (int j = 0, tile = blockIdx.x; tile < NTILES; tile += GRID, j++) {
            BAR_ALL();
            const int nb = (j + 1) & 1;
            const int nt_tile = tile + GRID;
            if (nt_tile < NTILES) {
                const long row0n = (long)nt_tile * TM;
                __half* Ah = AhB + nb * (ABUF_SZ / 2);
                #pragma unroll
                for (int s = 0; s < 2; s++) {
                    int r = lt + s * 64;
                    const float4* xr = (const float4*)(x + (row0n + r) * DIM);
                    float rn = 0.0f, sm_a = 0.0f, sh_a = 0.0f;
                    #pragma unroll
                    for (int jj = 0; jj < 16; jj++) {
                        float4 v = xr[jj];
                        rn = fmaf(v.x, v.x, rn); rn = fmaf(v.y, v.y, rn);
                        rn = fmaf(v.z, v.z, rn); rn = fmaf(v.w, v.w, rn);
                        __half2 h01 = __floats2half2_rn(v.x, v.y);
                        __half2 h23 = __floats2half2_rn(v.z, v.w);
                        float2 a01 = __half22float2(h01), a23 = __half22float2(h23);
                        sm_a += fabsf(v.x - a01.x) + fabsf(v.y - a01.y)
                              + fabsf(v.z - a23.x) + fabsf(v.w - a23.y);
                        sh_a += fabsf(a01.x) + fabsf(a01.y) + fabsf(a23.x) + fabsf(a23.y);
                        int off = r * RSTRIDE_A + jj * 4;
                        *(__half2*)(Ah + off)     = h01;
                        *(__half2*)(Ah + off + 2) = h23;
                    }
                    rn_s[nb * 128 + r] = rn;
                    thr_s[nb * 128 + r] = 2.0f * (0.051f * sm_a + 1.6e-5f * sh_a) + 2e-4f;
                }
            }
            // gather output of tile j-1 (codes published at BAR_ALL above)
            if (j > 0) {
                const int pb = (j - 1) & 1;
                #pragma unroll
                for (int s = 0; s < 2; s++) {
                    int r = lt + s * 64;
                    int k = codes_s[pb * 128 + r];
                    const float4* src = (const float4*)(dictT + k * 64);
                    float4* dst = (float4*)(out + (prev_row0 + r) * DIM);
                    #pragma unroll
                    for (int jj = 0; jj < 16; jj++) dst[jj] = src[jj];
                }
            }
            prev_row0 = (long)tile * TM;
        }
        BAR_ALL();                              // last tile's codes published
        {
            int last = (NTILES - 1 - blockIdx.x) / GRID;
            const int pb = last & 1;
            #pragma unroll
            for (int s = 0; s < 2; s++) {
                int r = lt + s * 64;
                int k = codes_s[pb * 128 + r];
                const float4* src = (const float4*)(dictT + k * 64);
                float4* dst = (float4*)(out + (prev_row0 + r) * DIM);
                #pragma unroll
                for (int jj = 0; jj < 16; jj++) dst[jj] = src[jj];
            }
        }
    }
}

__global__ __launch_bounds__(192) void finalize_kernel(float* __restrict__ out, int out_size) {
    const int tid = threadIdx.x;
    __shared__ float red[6];
    float s = (tid < GRID) ? g_partials[tid] : 0.0f;
    #pragma unroll
    for (int o = 16; o > 0; o >>= 1) s += __shfl_down_sync(0xffffffffu, s, o);
    if ((tid & 31) == 0) red[tid >> 5] = s;
    __syncthreads();
    if (tid == 0) {
        float t = 0.0f;
        #pragma unroll
        for (int i = 0; i < 6; i++) t += red[i];
        float m = t / (float)NELEM;
        if (out_size > NELEM) out[NELEM] = m + 0.25f * m;
    }
}

extern "C" void kernel_launch(void* const* d_in, const int* in_sizes, int n_in,
                              void* d_out, int out_size) {
    const float* x    = (const float*)d_in[0];   // [16,128,128,64]
    const float* dict = (const float*)d_in[1];   // [64,512]
    float* out = (float*)d_out;

    cudaFuncSetAttribute(vq_kernel, cudaFuncAttributeMaxDynamicSharedMemorySize, SM_SIZE);
    vq_kernel<<<GRID, NTHREADS, SM_SIZE>>>(x, dict, out);
    finalize_kernel<<<1, 192>>>(out, out_size);
}

// round 13
// speedup vs baseline: 1.5545x; 1.5545x over previous
#include <cuda_runtime.h>
#include <cuda_fp16.h>
#include <float.h>
#include <stdint.h>

#define NROWS   262144
#define DIM     64
#define NCODES  512
#define NELEM   (NROWS * DIM)
#define TM      128
#define NTILES  (NROWS / TM)     // 2048
#define GRID    152
#define NTHREADS 320             // 8 compute warps + 2 loader warps

#define RSTRIDE_A 72             // halves per padded A row (144 B)
#define RSTRIDE_B 64             // halves per B row (128 B)

// SMEM byte offsets
#define SM_AH    0               // A hi, 2 buffers x [128][72] f16  (36864)
#define SM_AM    36864           // A lo, 2 buffers                  (36864)
#define SM_BH    73728           // B hi [512][64] f16               (65536)
#define SM_BM    139264          // B lo                             (65536)
#define SM_NS    204800          // code norms f32[512]              (2048)
#define SM_RN    206848          // row norms, 2 x f32[128]          (1024)
#define SM_CODE  207872          // codes, 2 x int[128]              (1024)
#define SM_RD1   208896          // f32[128][8]                      (4096)
#define SM_RDK   212992          // int[128][8]                      (4096)
#define SM_SIZE  217088

#define ABUF_SZ  18432           // one A buffer (128*72*2)

__device__ float g_partials[GRID];

__device__ __forceinline__ uint32_t smem_u32(const void* p) {
    uint32_t a;
    asm("{ .reg .u64 t; cvta.to.shared.u64 t, %1; cvt.u32.u64 %0, t; }" : "=r"(a) : "l"(p));
    return a;
}

#define LDSM4(r, addr) \
    asm volatile("ldmatrix.sync.aligned.m8n8.x4.shared.b16 {%0,%1,%2,%3}, [%4];" \
        : "=r"((r)[0]), "=r"((r)[1]), "=r"((r)[2]), "=r"((r)[3]) : "r"(addr))

#define MMA16816(c, a, b0, b1) \
    asm volatile("mma.sync.aligned.m16n8k16.row.col.f32.f16.f16.f32 " \
        "{%0,%1,%2,%3}, {%4,%5,%6,%7}, {%8,%9}, {%0,%1,%2,%3};" \
        : "+f"((c)[0]), "+f"((c)[1]), "+f"((c)[2]), "+f"((c)[3]) \
        : "r"((a)[0]), "r"((a)[1]), "r"((a)[2]), "r"((a)[3]), "r"(b0), "r"(b1))

// named barriers: 3 = block-wide (320), 1 = compute-only (256)
#define BAR_ALL()  asm volatile("bar.sync 3, 320;" ::: "memory")
#define BAR_CMP()  asm volatile("bar.sync 1, 256;" ::: "memory")

extern __shared__ char smem_raw[];

__global__ __launch_bounds__(NTHREADS, 1) void vq_kernel(
    const float* __restrict__ x, const float* __restrict__ dict,
    float* __restrict__ out)
{
    char* sm = smem_raw;
    const uint32_t smu = smem_u32(sm);

    __half* Bh   = (__half*)(sm + SM_BH);
    __half* Bm   = (__half*)(sm + SM_BM);
    float*  ns_s = (float*)(sm + SM_NS);
    float*  rn_s = (float*)(sm + SM_RN);    // [2][128]
    int*    codes_s = (int*)(sm + SM_CODE); // [2][128]
    float*  rd1  = (float*)(sm + SM_RD1);
    int*    rdk  = (int*)(sm + SM_RDK);

    const int tid  = threadIdx.x;
    const int lane = tid & 31;

    // ---- build codebook splits (all 320 threads); dict is [D=64][K=512] ----
    {
        const float4* d4 = (const float4*)dict;
        for (int i = tid; i < 64 * 128; i += NTHREADS) {
            int d = i >> 7, kq = i & 127;
            float4 v = d4[d * 128 + kq];
            float vv[4] = {v.x, v.y, v.z, v.w};
            #pragma unroll
            for (int j = 0; j < 4; j++) {
                int k = kq * 4 + j;
                __half h = __float2half_rn(vv[j]);
                __half m = __float2half_rn(vv[j] - __half2float(h));
                Bh[k * RSTRIDE_B + d] = h;
                Bm[k * RSTRIDE_B + d] = m;
            }
        }
        for (int k = tid; k < NCODES; k += NTHREADS) {
            float s = 0.0f;
            #pragma unroll 8
            for (int d = 0; d < DIM; d++) {
                float v = dict[d * NCODES + k];
                s = fmaf(v, v, s);
            }
            ns_s[k] = s;
        }
    }
    __syncthreads();   // converged; last block-wide __syncthreads

    if (tid < 256) {
        // ================= COMPUTE WARPS =================
        const int w = tid >> 5;           // 0..7, owns codes [w*64, w*64+64)
        const int arow = (lane & 7) + (lane & 8);
        const int acol = (lane & 16) ? 8 : 0;
        const int bn   = (lane & 7) + ((lane & 16) >> 1);
        const int bk   = (lane & 8);
        const int crow = lane >> 2;
        const int ccol = 2 * (lane & 3);

        // B-stationary fragments in registers
        uint32_t BHf[4][4][4], BMf[4][4][4];
        {
            const uint32_t bHbase = smu + SM_BH + (uint32_t)((w * 64 + bn) * RSTRIDE_B + bk) * 2;
            const uint32_t bMbase = bHbase + (SM_BM - SM_BH);
            #pragma unroll
            for (int p = 0; p < 4; p++)
                #pragma unroll
                for (int kc = 0; kc < 4; kc++) {
                    uint32_t o = (uint32_t)(p * 16) * (RSTRIDE_B * 2) + kc * 32;
                    LDSM4(BHf[p][kc], bHbase + o);
                    LDSM4(BMf[p][kc], bMbase + o);
                }
        }
        // code-norm pairs for this lane's columns (constant across tiles)
        float nk0_r[8], nk1_r[8];
        #pragma unroll
        for (int nt = 0; nt < 8; nt++) {
            int n = w * 64 + nt * 8 + ccol;
            nk0_r[nt] = ns_s[n];
            nk1_r[nt] = ns_s[n + 1];
        }
        const uint32_t aOff0 = (uint32_t)(arow * RSTRIDE_A + acol) * 2;

        float loss_acc = 0.0f;

        #pragma unroll 1
        for (int j = 0, tile = blockIdx.x; tile < NTILES; tile += GRID, j++) {
            BAR_ALL();                         // A[j&1], rn[j&1] ready
            const int b = j & 1;
            const uint32_t aBase = smu + (uint32_t)(b * ABUF_SZ) + aOff0;

            #pragma unroll 1
            for (int rt = 0; rt < 8; rt++) {
                // ---- preload ALL A fragments first (R7 structure) ----
                uint32_t aH[4][4], aM[4][4];
                const uint32_t ab = aBase + (uint32_t)(rt * 16) * (RSTRIDE_A * 2);
                #pragma unroll
                for (int kc = 0; kc < 4; kc++) {
                    LDSM4(aH[kc], ab + kc * 32);
                    LDSM4(aM[kc], ab + (SM_AM - SM_AH) + kc * 32);
                }

                float f[8][4];
                #pragma unroll
                for (int nt = 0; nt < 8; nt++)
                    #pragma unroll
                    for (int q = 0; q < 4; q++) f[nt][q] = 0.0f;

                #pragma unroll
                for (int kc = 0; kc < 4; kc++) {
                    #pragma unroll
                    for (int nt = 0; nt < 8; nt++)
                        MMA16816(f[nt], aH[kc], BHf[nt >> 1][kc][(nt & 1) * 2], BHf[nt >> 1][kc][(nt & 1) * 2 + 1]);
                    #pragma unroll
                    for (int nt = 0; nt < 8; nt++)
                        MMA16816(f[nt], aM[kc], BHf[nt >> 1][kc][(nt & 1) * 2], BHf[nt >> 1][kc][(nt & 1) * 2 + 1]);
                    #pragma unroll
                    for (int nt = 0; nt < 8; nt++)
                        MMA16816(f[nt], aH[kc], BMf[nt >> 1][kc][(nt & 1) * 2], BMf[nt >> 1][kc][(nt & 1) * 2 + 1]);
                }

                const float rn0 = rn_s[b * 128 + rt * 16 + crow];
                const float rn1 = rn_s[b * 128 + rt * 16 + 8 + crow];
                float best0 = FLT_MAX, best1 = FLT_MAX;
                int   bk0 = 0, bk1 = 0;

                #pragma unroll
                for (int nt = 0; nt < 8; nt++) {
                    int n = w * 64 + nt * 8 + ccol;
                    float d00 = fmaf(-2.0f, f[nt][0], rn0 + nk0_r[nt]);
                    float d01 = fmaf(-2.0f, f[nt][1], rn0 + nk1_r[nt]);
                    float d10 = fmaf(-2.0f, f[nt][2], rn1 + nk0_r[nt]);
                    float d11 = fmaf(-2.0f, f[nt][3], rn1 + nk1_r[nt]);
                    if (d00 < best0) { best0 = d00; bk0 = n; }
                    if (d01 < best0) { best0 = d01; bk0 = n + 1; }
                    if (d10 < best1) { best1 = d10; bk1 = n; }
                    if (d11 < best1) { best1 = d11; bk1 = n + 1; }
                }

                #pragma unroll
                for (int off = 1; off <= 2; off <<= 1) {
                    float od0 = __shfl_xor_sync(0xffffffffu, best0, off);
                    int   ok0 = __shfl_xor_sync(0xffffffffu, bk0, off);
                    if (od0 < best0 || (od0 == best0 && ok0 < bk0)) { best0 = od0; bk0 = ok0; }
                    float od1 = __shfl_xor_sync(0xffffffffu, best1, off);
                    int   ok1 = __shfl_xor_sync(0xffffffffu, bk1, off);
                    if (od1 < best1 || (od1 == best1 && ok1 < bk1)) { best1 = od1; bk1 = ok1; }
                }
                if ((lane & 3) == 0) {
                    int ra = rt * 16 + crow;
                    rd1[ra * 8 + w] = best0;        rdk[ra * 8 + w] = bk0;
                    rd1[(ra + 8) * 8 + w] = best1;  rdk[(ra + 8) * 8 + w] = bk1;
                }
            }
            BAR_CMP();                          // rd1/rdk complete (compute only)

            if (tid < TM) {
                float bd = rd1[tid * 8];
                int   bkk = rdk[tid * 8];
                #pragma unroll
                for (int q = 1; q < 8; q++) {
                    float dv = rd1[tid * 8 + q];
                    int   kk = rdk[tid * 8 + q];
                    if (dv < bd || (dv == bd && kk < bkk)) { bd = dv; bkk = kk; }
                }
                codes_s[b * 128 + tid] = bkk;
                loss_acc += bd;                 // ||x - q||^2 for this row
            }
        }
        BAR_ALL();                              // publish last codes to loaders

        // ---- per-CTA loss reduction (compute threads only) ----
        float v = loss_acc;
        #pragma unroll
        for (int o = 16; o > 0; o >>= 1) v += __shfl_down_sync(0xffffffffu, v, o);
        if (lane == 0) rd1[w] = v;
        BAR_CMP();
        if (tid == 0) {
            float t = 0.0f;
            #pragma unroll
            for (int i = 0; i < 8; i++) t += rd1[i];
            g_partials[blockIdx.x] = t;
        }
    } else {
        // ================= LOADER WARPS (tid 256..319) =================
        const int lt = tid - 256;               // 0..63, owns rows lt and lt+64
        __half* AhB = (__half*)(sm + SM_AH);
        __half* AmB = (__half*)(sm + SM_AM);

        // prologue: fill buffer 0 with tile blockIdx.x
        {
            const long row0 = (long)blockIdx.x * TM;
            #pragma unroll
            for (int s = 0; s < 2; s++) {
                int r = lt + s * 64;
                const float4* xr = (const float4*)(x + (row0 + r) * DIM);
                float rn = 0.0f;
                #pragma unroll
                for (int jj = 0; jj < 16; jj++) {
                    float4 v = xr[jj];
                    rn = fmaf(v.x, v.x, rn); rn = fmaf(v.y, v.y, rn);
                    rn = fmaf(v.z, v.z, rn); rn = fmaf(v.w, v.w, rn);
                    __half h0 = __float2half_rn(v.x), h1 = __float2half_rn(v.y);
                    __half h2 = __float2half_rn(v.z), h3 = __float2half_rn(v.w);
                    __half m0 = __float2half_rn(v.x - __half2float(h0));
                    __half m1 = __float2half_rn(v.y - __half2float(h1));
                    __half m2 = __float2half_rn(v.z - __half2float(h2));
                    __half m3 = __float2half_rn(v.w - __half2float(h3));
                    int off = r * RSTRIDE_A + jj * 4;
                    *(__half2*)(AhB + off)     = __halves2half2(h0, h1);
                    *(__half2*)(AhB + off + 2) = __halves2half2(h2, h3);
                    *(__half2*)(AmB + off)     = __halves2half2(m0, m1);
                    *(__half2*)(AmB + off + 2) = __halves2half2(m2, m3);
                }
                rn_s[r] = rn;
            }
        }

        long prev_row0 = 0;
        #pragma unroll 1
        for (int j = 0, tile = blockIdx.x; tile < NTILES; tile += GRID, j++) {
            BAR_ALL();
            // load tile j+1 into buffer (j+1)&1 (overlaps compute of tile j)
            const int nb = (j + 1) & 1;
            const int nt_tile = tile + GRID;
            if (nt_tile < NTILES) {
                const long row0n = (long)nt_tile * TM;
                __half* Ah = AhB + nb * (ABUF_SZ / 2);
                __half* Am = AmB + nb * (ABUF_SZ / 2);
                #pragma unroll
                for (int s = 0; s < 2; s++) {
                    int r = lt + s * 64;
                    const float4* xr = (const float4*)(x + (row0n + r) * DIM);
                    float rn = 0.0f;
                    #pragma unroll
                    for (int jj = 0; jj < 16; jj++) {
                        float4 v = xr[jj];
                        rn = fmaf(v.x, v.x, rn); rn = fmaf(v.y, v.y, rn);
                        rn = fmaf(v.z, v.z, rn); rn = fmaf(v.w, v.w, rn);
                        __half h0 = __float2half_rn(v.x), h1 = __float2half_rn(v.y);
                        __half h2 = __float2half_rn(v.z), h3 = __float2half_rn(v.w);
                        __half m0 = __float2half_rn(v.x - __half2float(h0));
                        __half m1 = __float2half_rn(v.y - __half2float(h1));
                        __half m2 = __float2half_rn(v.z - __half2float(h2));
                        __half m3 = __float2half_rn(v.w - __half2float(h3));
                        int off = r * RSTRIDE_A + jj * 4;
                        *(__half2*)(Ah + off)     = __halves2half2(h0, h1);
                        *(__half2*)(Ah + off + 2) = __halves2half2(h2, h3);
                        *(__half2*)(Am + off)     = __halves2half2(m0, m1);
                        *(__half2*)(Am + off + 2) = __halves2half2(m2, m3);
                    }
                    rn_s[nb * 128 + r] = rn;
                }
            }
            // gather output of tile j-1 (codes published at BAR_ALL above)
            if (j > 0) {
                const int pb = (j - 1) & 1;
                #pragma unroll
                for (int s = 0; s < 2; s++) {
                    int r = lt + s * 64;
                    int k = codes_s[pb * 128 + r];
                    const __half2* bh = (const __half2*)(Bh + k * RSTRIDE_B);
                    const __half2* bm = (const __half2*)(Bm + k * RSTRIDE_B);
                    float4* dst = (float4*)(out + (prev_row0 + r) * DIM);
                    #pragma unroll
                    for (int jj = 0; jj < 16; jj++) {
                        float2 fa = __half22float2(bh[jj * 2]);
                        float2 fb = __half22float2(bh[jj * 2 + 1]);
                        float2 ga = __half22float2(bm[jj * 2]);
                        float2 gb = __half22float2(bm[jj * 2 + 1]);
                        float4 o;
                        o.x = fa.x + ga.x; o.y = fa.y + ga.y;
                        o.z = fb.x + gb.x; o.w = fb.y + gb.y;
                        dst[jj] = o;
                    }
                }
            }
            prev_row0 = (long)tile * TM;
        }
        BAR_ALL();                              // last tile's codes published
        // final gather
        {
            int last = (NTILES - 1 - blockIdx.x) / GRID;
            const int pb = last & 1;
            #pragma unroll
            for (int s = 0; s < 2; s++) {
                int r = lt + s * 64;
                int k = codes_s[pb * 128 + r];
                const __half2* bh = (const __half2*)(Bh + k * RSTRIDE_B);
                const __half2* bm = (const __half2*)(Bm + k * RSTRIDE_B);
                float4* dst = (float4*)(out + (prev_row0 + r) * DIM);
                #pragma unroll
                for (int jj = 0; jj < 16; jj++) {
                    float2 fa = __half22float2(bh[jj * 2]);
                    float2 fb = __half22float2(bh[jj * 2 + 1]);
                    float2 ga = __half22float2(bm[jj * 2]);
                    float2 gb = __half22float2(bm[jj * 2 + 1]);
                    float4 o;
                    o.x = fa.x + ga.x; o.y = fa.y + ga.y;
                    o.z = fb.x + gb.x; o.w = fb.y + gb.y;
                    dst[jj] = o;
                }
            }
        }
    }
}

__global__ __launch_bounds__(192) void finalize_kernel(float* __restrict__ out, int out_size) {
    const int tid = threadIdx.x;
    __shared__ float red[6];
    float s = (tid < GRID) ? g_partials[tid] : 0.0f;
    #pragma unroll
    for (int o = 16; o > 0; o >>= 1) s += __shfl_down_sync(0xffffffffu, s, o);
    if ((tid & 31) == 0) red[tid >> 5] = s;
    __syncthreads();
    if (tid == 0) {
        float t = 0.0f;
        #pragma unroll
        for (int i = 0; i < 6; i++) t += red[i];
        float m = t / (float)NELEM;
        if (out_size > NELEM) out[NELEM] = m + 0.25f * m;
    }
}

extern "C" void kernel_launch(void* const* d_in, const int* in_sizes, int n_in,
                              void* d_out, int out_size) {
    const float* x    = (const float*)d_in[0];   // [16,128,128,64]
    const float* dict = (const float*)d_in[1];   // [64,512]
    float* out = (float*)d_out;

    cudaFuncSetAttribute(vq_kernel, cudaFuncAttributeMaxDynamicSharedMemorySize, SM_SIZE);
    vq_kernel<<<GRID, NTHREADS, SM_SIZE>>>(x, dict, out);
    finalize_kernel<<<1, 192>>>(out, out_size);
}

// round 14
// speedup vs baseline: 2.0750x; 1.3349x over previous
#include <cuda_runtime.h>
#include <cuda_fp16.h>
#include <float.h>
#include <stdint.h>

#define NROWS   262144
#define DIM     64
#define NCODES  512
#define NELEM   (NROWS * DIM)
#define TM      128
#define NTILES  (NROWS / TM)     // 2048
#define GRID    152
#define NTHREADS 256

#define RSTRIDE 72               // halves per padded row (144 B: conflict-free ldmatrix)

// SMEM byte offsets
#define SM_AH    0                       // A hi  [128][72] f16  (18432)
#define SM_AM    18432                   // A lo                 (18432)
#define SM_BH    36864                   // B hi  [512][72] f16  (73728)
#define SM_BM    110592                  // B lo                 (73728)
#define SM_NS    184320                  // code norms f32[512]  (2048)
#define SM_RN    186368                  // row norms  f32[128]  (512)
#define SM_CODE  186880                  // codes int[128]       (512)
#define SM_REDD  187392                  // f32[128][8]          (4096)
#define SM_REDK  191488                  // int[128][8]          (4096)
#define SM_SIZE  195584

__device__ float g_partials[GRID];
__device__ unsigned int g_done = 0;

__device__ __forceinline__ uint32_t smem_u32(const void* p) {
    uint32_t a;
    asm("{ .reg .u64 t; cvta.to.shared.u64 t, %1; cvt.u32.u64 %0, t; }" : "=r"(a) : "l"(p));
    return a;
}

#define LDSM4(r, addr) \
    asm volatile("ldmatrix.sync.aligned.m8n8.x4.shared.b16 {%0,%1,%2,%3}, [%4];" \
        : "=r"((r)[0]), "=r"((r)[1]), "=r"((r)[2]), "=r"((r)[3]) : "r"(addr))

#define MMA16816(c, a, b0, b1) \
    asm volatile("mma.sync.aligned.m16n8k16.row.col.f32.f16.f16.f32 " \
        "{%0,%1,%2,%3}, {%4,%5,%6,%7}, {%8,%9}, {%0,%1,%2,%3};" \
        : "+f"((c)[0]), "+f"((c)[1]), "+f"((c)[2]), "+f"((c)[3]) \
        : "r"((a)[0]), "r"((a)[1]), "r"((a)[2]), "r"((a)[3]), "r"(b0), "r"(b1))

extern __shared__ char smem_raw[];

__global__ __launch_bounds__(NTHREADS, 1) void vq_kernel(
    const float* __restrict__ x, const float* __restrict__ dict,
    float* __restrict__ out, int out_size)
{
    char* sm = smem_raw;
    const uint32_t smu = smem_u32(sm);

    __half* Bh      = (__half*)(sm + SM_BH);
    __half* Bm      = (__half*)(sm + SM_BM);
    __half* Ah      = (__half*)(sm + SM_AH);
    __half* Am      = (__half*)(sm + SM_AM);
    float*  ns_s    = (float*)(sm + SM_NS);
    float*  rn_s    = (float*)(sm + SM_RN);
    int*    codes_s = (int*)(sm + SM_CODE);
    float*  redd    = (float*)(sm + SM_REDD);   // [row][warp]
    int*    redk    = (int*)(sm + SM_REDK);

    const int tid  = threadIdx.x;
    const int w    = tid >> 5;
    const int lane = tid & 31;

    // ---- build codebook splits in SMEM (dict is [D=64][K=512], k fastest) ----
    {
        const float4* d4 = (const float4*)dict;
        for (int i = tid; i < 64 * 128; i += NTHREADS) {
            int d = i >> 7, kq = i & 127;
            float4 v = d4[d * 128 + kq];
            float vv[4] = {v.x, v.y, v.z, v.w};
            #pragma unroll
            for (int j = 0; j < 4; j++) {
                int k = kq * 4 + j;
                __half h = __float2half_rn(vv[j]);
                __half m = __float2half_rn(vv[j] - __half2float(h));
                Bh[k * RSTRIDE + d] = h;
                Bm[k * RSTRIDE + d] = m;
            }
        }
        for (int k = tid; k < NCODES; k += NTHREADS) {
            float s = 0.0f;
            #pragma unroll 8
            for (int d = 0; d < DIM; d++) {
                float v = dict[d * NCODES + k];
                s = fmaf(v, v, s);
            }
            ns_s[k] = s;
        }
    }
    __syncthreads();

    // lane-constant fragment addressing
    const int arow = (lane & 7) + (lane & 8);
    const int bn   = (lane & 7) + ((lane & 16) >> 1);
    const int bk   = (lane & 8);
    const int acol = (lane & 16) ? 8 : 0;
    const int crow = lane >> 2;
    const int ccol = 2 * (lane & 3);

    // ---- B-stationary: each warp owns codes [w*64, w*64+64), fragments in regs ----
    uint32_t BHf[4][4][4];   // [p=16-code tile][kc][frag]
    uint32_t BMf[4][4][4];
    {
        const uint32_t bHbase = smu + SM_BH + (uint32_t)((w * 64 + bn) * RSTRIDE + bk) * 2;
        const uint32_t bMbase = bHbase + (SM_BM - SM_BH);
        #pragma unroll
        for (int p = 0; p < 4; p++)
            #pragma unroll
            for (int kc = 0; kc < 4; kc++) {
                uint32_t o = (uint32_t)(p * 16) * (RSTRIDE * 2) + kc * 32;
                LDSM4(BHf[p][kc], bHbase + o);
                LDSM4(BMf[p][kc], bMbase + o);
            }
    }

    // code-norm pairs for this lane's columns (constant across tiles)
    float nk0_r[8], nk1_r[8];
    #pragma unroll
    for (int nt = 0; nt < 8; nt++) {
        int n = w * 64 + nt * 8 + ccol;
        nk0_r[nt] = ns_s[n];
        nk1_r[nt] = ns_s[n + 1];
    }

    const uint32_t aHbase0 = smu + SM_AH + (uint32_t)(arow * RSTRIDE + acol) * 2;

    const int r2 = tid >> 1;     // row owned for load/gather
    const int ch = tid & 1;      // 32-col half

    float loss_acc = 0.0f;

    #pragma unroll 1
    for (int tile = blockIdx.x; tile < NTILES; tile += GRID) {
        const long row0 = (long)tile * TM;

        // ---- load x tile, split to fp16 hi/lo, row norms ----
        {
            const float4* xr = (const float4*)(x + (row0 + r2) * DIM + ch * 32);
            float rnp = 0.0f;
            #pragma unroll
            for (int j = 0; j < 8; j++) {
                float4 v = xr[j];
                rnp = fmaf(v.x, v.x, rnp); rnp = fmaf(v.y, v.y, rnp);
                rnp = fmaf(v.z, v.z, rnp); rnp = fmaf(v.w, v.w, rnp);
                __half h0 = __float2half_rn(v.x), h1 = __float2half_rn(v.y);
                __half h2 = __float2half_rn(v.z), h3 = __float2half_rn(v.w);
                __half m0 = __float2half_rn(v.x - __half2float(h0));
                __half m1 = __float2half_rn(v.y - __half2float(h1));
                __half m2 = __float2half_rn(v.z - __half2float(h2));
                __half m3 = __float2half_rn(v.w - __half2float(h3));
                int off = r2 * RSTRIDE + ch * 32 + j * 4;
                *(__half2*)(Ah + off)     = __halves2half2(h0, h1);
                *(__half2*)(Ah + off + 2) = __halves2half2(h2, h3);
                *(__half2*)(Am + off)     = __halves2half2(m0, m1);
                *(__half2*)(Am + off + 2) = __halves2half2(m2, m3);
            }
            float rno = __shfl_xor_sync(0xffffffffu, rnp, 1);
            if (ch == 0) rn_s[r2] = rnp + rno;
        }
        // prefetch next tile's x block to L2 (one 128B line per thread)
        if (tile + GRID < NTILES) {
            const float* np = x + ((long)(tile + GRID) * TM + r2) * DIM + ch * 32;
            asm volatile("prefetch.global.L2 [%0];" :: "l"(np));
        }
        __syncthreads();

        // ---- stream 8 row-tiles of 16 against the warp's resident 64 codes ----
        #pragma unroll 1
        for (int rt = 0; rt < 8; rt++) {
            uint32_t aH[4][4], aM[4][4];
            const uint32_t ab = aHbase0 + (uint32_t)(rt * 16) * (RSTRIDE * 2);
            #pragma unroll
            for (int kc = 0; kc < 4; kc++) {
                LDSM4(aH[kc], ab + kc * 32);
                LDSM4(aM[kc], ab + (SM_AM - SM_AH) + kc * 32);
            }

            float f[8][4];
            #pragma unroll
            for (int nt = 0; nt < 8; nt++)
                #pragma unroll
                for (int q = 0; q < 4; q++) f[nt][q] = 0.0f;

            #pragma unroll
            for (int kc = 0; kc < 4; kc++) {
                #pragma unroll
                for (int nt = 0; nt < 8; nt++)
                    MMA16816(f[nt], aH[kc], BHf[nt >> 1][kc][(nt & 1) * 2], BHf[nt >> 1][kc][(nt & 1) * 2 + 1]);
                #pragma unroll
                for (int nt = 0; nt < 8; nt++)
                    MMA16816(f[nt], aM[kc], BHf[nt >> 1][kc][(nt & 1) * 2], BHf[nt >> 1][kc][(nt & 1) * 2 + 1]);
                #pragma unroll
                for (int nt = 0; nt < 8; nt++)
                    MMA16816(f[nt], aH[kc], BMf[nt >> 1][kc][(nt & 1) * 2], BMf[nt >> 1][kc][(nt & 1) * 2 + 1]);
            }

            const float rn0 = rn_s[rt * 16 + crow];
            const float rn1 = rn_s[rt * 16 + 8 + crow];
            float best0 = FLT_MAX, best1 = FLT_MAX;
            int   bk0 = 0, bk1 = 0;

            #pragma unroll
            for (int nt = 0; nt < 8; nt++) {
                int n = w * 64 + nt * 8 + ccol;
                float d00 = fmaf(-2.0f, f[nt][0], rn0 + nk0_r[nt]);
                float d01 = fmaf(-2.0f, f[nt][1], rn0 + nk1_r[nt]);
                float d10 = fmaf(-2.0f, f[nt][2], rn1 + nk0_r[nt]);
                float d11 = fmaf(-2.0f, f[nt][3], rn1 + nk1_r[nt]);
                if (d00 < best0) { best0 = d00; bk0 = n; }
                if (d01 < best0) { best0 = d01; bk0 = n + 1; }
                if (d10 < best1) { best1 = d10; bk1 = n; }
                if (d11 < best1) { best1 = d11; bk1 = n + 1; }
            }

            // merge over lane bits 0-1 (interleaved code cols)
            #pragma unroll
            for (int off = 1; off <= 2; off <<= 1) {
                float od0 = __shfl_xor_sync(0xffffffffu, best0, off);
                int   ok0 = __shfl_xor_sync(0xffffffffu, bk0, off);
                if (od0 < best0 || (od0 == best0 && ok0 < bk0)) { best0 = od0; bk0 = ok0; }
                float od1 = __shfl_xor_sync(0xffffffffu, best1, off);
                int   ok1 = __shfl_xor_sync(0xffffffffu, bk1, off);
                if (od1 < best1 || (od1 == best1 && ok1 < bk1)) { best1 = od1; bk1 = ok1; }
            }
            if ((lane & 3) == 0) {
                int row_a = rt * 16 + crow;
                redd[row_a * 8 + w] = best0;  redk[row_a * 8 + w] = bk0;
                redd[(row_a + 8) * 8 + w] = best1;  redk[(row_a + 8) * 8 + w] = bk1;
            }
        }
        __syncthreads();

        // ---- cross-warp argmin per row (threads 0-127) ----
        if (tid < TM) {
            float bd = redd[tid * 8];
            int   bkk = redk[tid * 8];
            #pragma unroll
            for (int j = 1; j < 8; j++) {
                float dv = redd[tid * 8 + j];
                int   kk = redk[tid * 8 + j];
                if (dv < bd || (dv == bd && kk < bkk)) { bd = dv; bkk = kk; }
            }
            codes_s[tid] = bkk;
            loss_acc += bd;                 // ||x - q||^2 for this row
        }
        __syncthreads();

        // ---- gather output: q = h + m (reconstructed codeword) ----
        {
            const int k = codes_s[r2];
            float4* dst = (float4*)(out + (row0 + r2) * DIM + ch * 32);
            #pragma unroll
            for (int j = 0; j < 8; j++) {
                int d0 = k * RSTRIDE + ch * 32 + j * 4;
                __half2 ha = *(const __half2*)(Bh + d0);
                __half2 hb = *(const __half2*)(Bh + d0 + 2);
                __half2 ma = *(const __half2*)(Bm + d0);
                __half2 mb = *(const __half2*)(Bm + d0 + 2);
                float2 fa = __half22float2(ha), fb = __half22float2(hb);
                float2 ga = __half22float2(ma), gb = __half22float2(mb);
                float4 o;
                o.x = fa.x + ga.x; o.y = fa.y + ga.y;
                o.z = fb.x + gb.x; o.w = fb.y + gb.y;
                dst[j] = o;
            }
        }
        // ordering vs next tile: 2 syncs before codes_s rewrite; Ah/Am not read by gather
    }

    // ---- per-CTA loss reduction (deterministic) ----
    __syncthreads();
    float v = loss_acc;
    #pragma unroll
    for (int o = 16; o > 0; o >>= 1) v += __shfl_down_sync(0xffffffffu, v, o);
    if (lane == 0) rn_s[w] = v;
    __syncthreads();
    if (tid == 0) {
        float t = 0.0f;
        #pragma unroll
        for (int i = 0; i < 8; i++) t += rn_s[i];
        g_partials[blockIdx.x] = t;
        __threadfence();
        unsigned int old = atomicAdd(&g_done, 1u);
        if (old == GRID - 1) {
            g_done = 0;                      // reset for next graph replay
            float s = 0.0f;
            #pragma unroll 8
            for (int i = 0; i < GRID; i++) s += g_partials[i];
            float m = s / (float)NELEM;
            if (out_size > NELEM) out[NELEM] = m + 0.25f * m;
        }
    }
}

extern "C" void kernel_launch(void* const* d_in, const int* in_sizes, int n_in,
                              void* d_out, int out_size) {
    const float* x    = (const float*)d_in[0];   // [16,128,128,64]
    const float* dict = (const float*)d_in[1];   // [64,512]
    float* out = (float*)d_out;

    cudaFuncSetAttribute(vq_kernel, cudaFuncAttributeMaxDynamicSharedMemorySize, SM_SIZE);
    vq_kernel<<<GRID, NTHREADS, SM_SIZE>>>(x, dict, out, out_size);
}